// round 15
// baseline (speedup 1.0000x reference)
#include <cuda_runtime.h>
#include <math.h>

#define Bb   2
#define Ss   2048
#define HIDD 2048
#define NHH  8
#define HDD  256
#define BSr  (Bb*Ss)      // 4096 rows
#define HALF (HDD/2)      // 128

// ---------------- scratch (static device memory; no allocation) ----------------
__device__ float g_Q[(size_t)BSr * HIDD];          // 32 MB  [b*S+s, h*HD+d]
__device__ float g_K[(size_t)BSr * HDD];           // 4 MB   [b*S+s, d]
__device__ float g_V[(size_t)BSr * HDD];           // 4 MB
__device__ float g_O[(size_t)BSr * HIDD];          // 32 MB  attn@V result in [b,s,h*HD+d]
__device__ float g_attn_scratch[(size_t)Bb * NHH * Ss * Ss];  // 256 MB fallback

// ---------------- f32x2 packed helpers ----------------
__device__ __forceinline__ void unpack2(unsigned long long v, float& lo, float& hi) {
    asm("mov.b64 {%0, %1}, %2;" : "=f"(lo), "=f"(hi) : "l"(v));
}
__device__ __forceinline__ void fma2(unsigned long long& d, unsigned long long a, unsigned long long b) {
    asm("fma.rn.f32x2 %0, %1, %2, %0;" : "+l"(d) : "l"(a), "l"(b));
}

// ---------------- 128x128x8 SGEMM tile ----------------
// Ping-pong smem + register prefetch; A stored DUPLICATED in smem so a single
// LDS.64 yields the packed {a,a} FFMA2 operand (no MOV-pair packing in the hot loop).
// NT=false: C = A[M,K] * B[K,N]      (B row-major KxN)
// NT=true : C = A[M,K] * B[N,K]^T    (B row-major NxK)
template <bool NT>
__device__ __forceinline__ void sgemm_tile(
    const float* __restrict__ A, int lda,
    const float* __restrict__ Bm, int ldb,
    float* __restrict__ C, int ldc,
    int Kdim, int brow, int bcol, float scale)
{
    __shared__ float As[2][8][256];   // duplicated: As[.][k][2r] == As[.][k][2r+1]
    __shared__ float Bs[2][8][128];
    const int t    = threadIdx.x;
    const int tcol = t & 15;
    const int trow = t >> 4;

    unsigned long long acc[8][4];
#pragma unroll
    for (int i = 0; i < 8; i++)
#pragma unroll
        for (int j = 0; j < 4; j++) acc[i][j] = 0ull;

    const int ar = t >> 1;          // 0..127
    const int ac = (t & 1) * 4;     // 0 or 4
    const float* Abase = A + (size_t)(brow * 128 + ar) * lda + ac;
    const int br_n = t >> 5;            // NT=false: k row 0..7
    const int bc_n = (t & 31) * 4;      // NT=false: n col
    const int bn_t = t >> 1;            // NT=true : n row 0..127
    const int bk_t = (t & 1) * 4;       // NT=true : k col 0 or 4
    const float* Bbase = NT ? (Bm + (size_t)(bcol * 128 + bn_t) * ldb + bk_t)
                            : (Bm + (size_t)br_n * ldb + bcol * 128 + bc_n);

    const int nit = Kdim >> 3;

    float4 va, vb;
    va = *(const float4*)(Abase);
    vb = *(const float4*)(Bbase);
    {
        float2 d0 = make_float2(va.x, va.x), d1 = make_float2(va.y, va.y);
        float2 d2 = make_float2(va.z, va.z), d3 = make_float2(va.w, va.w);
        *(float2*)&As[0][ac + 0][2 * ar] = d0; *(float2*)&As[0][ac + 1][2 * ar] = d1;
        *(float2*)&As[0][ac + 2][2 * ar] = d2; *(float2*)&As[0][ac + 3][2 * ar] = d3;
    }
    if (!NT) {
        *(float4*)&Bs[0][br_n][bc_n] = vb;
    } else {
        Bs[0][bk_t + 0][bn_t] = vb.x; Bs[0][bk_t + 1][bn_t] = vb.y;
        Bs[0][bk_t + 2][bn_t] = vb.z; Bs[0][bk_t + 3][bn_t] = vb.w;
    }
    __syncthreads();

    for (int g = 0; g < nit; g++) {
        const int cur = g & 1;
        if (g + 1 < nit) {
            const int k = (g + 1) * 8;
            va = *(const float4*)(Abase + k);
            vb = NT ? *(const float4*)(Bbase + k)
                    : *(const float4*)(Bbase + (size_t)k * ldb);
        }

#pragma unroll
        for (int k = 0; k < 8; k++) {
            unsigned long long aa[8], bb[4];
#pragma unroll
            for (int j = 0; j < 4; j++)
                bb[j] = *(const unsigned long long*)&Bs[cur][k][2 * tcol + 32 * j];
#pragma unroll
            for (int i = 0; i < 8; i++)
                aa[i] = *(const unsigned long long*)&As[cur][k][2 * (trow + 16 * i)];
#pragma unroll
            for (int i = 0; i < 8; i++)
#pragma unroll
                for (int j = 0; j < 4; j++)
                    fma2(acc[i][j], aa[i], bb[j]);
        }

        if (g + 1 < nit) {
            const int nxt = cur ^ 1;
            float2 d0 = make_float2(va.x, va.x), d1 = make_float2(va.y, va.y);
            float2 d2 = make_float2(va.z, va.z), d3 = make_float2(va.w, va.w);
            *(float2*)&As[nxt][ac + 0][2 * ar] = d0; *(float2*)&As[nxt][ac + 1][2 * ar] = d1;
            *(float2*)&As[nxt][ac + 2][2 * ar] = d2; *(float2*)&As[nxt][ac + 3][2 * ar] = d3;
            if (!NT) {
                *(float4*)&Bs[nxt][br_n][bc_n] = vb;
            } else {
                Bs[nxt][bk_t + 0][bn_t] = vb.x; Bs[nxt][bk_t + 1][bn_t] = vb.y;
                Bs[nxt][bk_t + 2][bn_t] = vb.z; Bs[nxt][bk_t + 3][bn_t] = vb.w;
            }
        }
        __syncthreads();
    }

#pragma unroll
    for (int i = 0; i < 8; i++) {
        const size_t r = (size_t)(brow * 128 + trow + 16 * i);
#pragma unroll
        for (int j = 0; j < 4; j++) {
            float lo, hi;
            unpack2(acc[i][j], lo, hi);
            const int cl = bcol * 128 + 2 * tcol + 32 * j;
            C[r * ldc + cl]     = lo * scale;
            C[r * ldc + cl + 1] = hi * scale;
        }
    }
}

// ---------------- QKV projections ----------------
__global__ __launch_bounds__(256) void qkv_kernel(
    const float* __restrict__ x,
    const float* __restrict__ wq,
    const float* __restrict__ wk,
    const float* __restrict__ wv)
{
    const int id = blockIdx.x;
    if (id < 512) {
        sgemm_tile<false>(x, HIDD, wq, HIDD, g_Q, HIDD, HIDD, id >> 4, id & 15, 1.f);
    } else if (id < 576) {
        const int m = id - 512;
        sgemm_tile<false>(x, HIDD, wk, HDD, g_K, HDD, HIDD, m >> 1, m & 1, 1.f);
    } else {
        const int m = id - 576;
        sgemm_tile<false>(x, HIDD, wv, HDD, g_V, HDD, HIDD, m >> 1, m & 1, 1.f);
    }
}

// ---------------- RoPE (fast: exact-fp64 invf via binary exponentiation, Cody-Waite
// mod-2pi reduction in fp64, fp32 sincos on the reduced argument) ----------------
__constant__ double c_BPOW[7] = {
    0.9305720409297047,    // base^1,  base = 10000^(-1/128)
    0.8659643233600654,    // base^2
    0.7498942093324559,    // base^4
    0.5623413251903491,    // base^8
    0.31622776601683794,   // base^16
    0.1,                   // base^32
    0.010000000000000002   // base^64
};
#define TWO_PI_HI 6.283185307179586
#define TWO_PI_LO 2.4492935982947064e-16
#define INV_2PI   0.15915494309189535

__device__ __forceinline__ void rope_cs(int p, int pos, float& c, float& s)
{
    double invf = 1.0;
#pragma unroll
    for (int k = 0; k < 7; k++)
        if (p & (1 << k)) invf *= c_BPOW[k];
    const double phase = (double)pos * invf;
    const double q = floor(phase * INV_2PI + 0.5);
    double r = fma(-TWO_PI_HI, q, phase);
    r = fma(-TWO_PI_LO, q, r);
    const float rf = (float)r;
    c = cosf(rf);
    s = sinf(rf);
}

__global__ void rope_kernel(const int* __restrict__ pos_ids)
{
    const int gid = blockIdx.x * blockDim.x + threadIdx.x;
    const int TQ = BSr * NHH * HALF;   // 4,194,304
    const int TK = BSr * HALF;         //   524,288
    if (gid < TQ) {
        const int p = gid & (HALF - 1);
        const int h = (gid >> 7) & (NHH - 1);
        const int r = gid >> 10;
        float c, s;
        rope_cs(p, pos_ids[r], c, s);
        float* q = g_Q + (size_t)r * HIDD + h * HDD;
        const float v1 = q[p], v2 = q[p + HALF];
        q[p]        = v1 * c - v2 * s;
        q[p + HALF] = v2 * c + v1 * s;
    } else if (gid < TQ + TK) {
        const int g2 = gid - TQ;
        const int p = g2 & (HALF - 1);
        const int r = g2 >> 7;
        float c, s;
        rope_cs(p, pos_ids[r], c, s);
        float* kk = g_K + (size_t)r * HDD;
        const float v1 = kk[p], v2 = kk[p + HALF];
        kk[p]        = v1 * c - v2 * s;
        kk[p + HALF] = v2 * c + v1 * s;
    }
}

// ---------------- scores = Q K^T / 16 (causal tiles only) ----------------
__global__ __launch_bounds__(256) void scores_kernel(float* attn_out)
{
    const int bcol = blockIdx.x, brow = blockIdx.y, bh = blockIdx.z;
    if (bcol > brow) return;   // fully-masked tile: softmax writes zeros there
    float* attn = attn_out ? attn_out : g_attn_scratch;
    const int b = bh >> 3, h = bh & 7;
    const float* A  = g_Q + (size_t)b * Ss * HIDD + h * HDD;
    const float* Bm = g_K + (size_t)b * Ss * HDD;
    float* C = attn + (size_t)bh * Ss * Ss;
    sgemm_tile<true>(A, HIDD, Bm, HDD, C, Ss, HDD, brow, bcol, 0.0625f);
}

// ---------------- causal row softmax (one pass, register-cached) ----------------
__global__ __launch_bounds__(256) void softmax_kernel(float* attn_out)
{
    float* attn = attn_out ? attn_out : g_attn_scratch;
    const int R = blockIdx.x;          // (b*NH+h)*S + i
    const int i = R & (Ss - 1);
    float* row = attn + (size_t)R * Ss;
    const int n = i + 1;
    const int t = threadIdx.x;

    float v[8];
    float m = -1e30f;
#pragma unroll
    for (int it = 0; it < 8; it++) {
        const int j = t + (it << 8);
        v[it] = (j < n) ? row[j] : -1e30f;
        m = fmaxf(m, v[it]);
    }
#pragma unroll
    for (int o = 16; o; o >>= 1) m = fmaxf(m, __shfl_xor_sync(0xffffffffu, m, o));
    __shared__ float red[8];
    if ((t & 31) == 0) red[t >> 5] = m;
    __syncthreads();
    float mm = red[0];
#pragma unroll
    for (int w = 1; w < 8; w++) mm = fmaxf(mm, red[w]);
    __syncthreads();

    float sum = 0.f;
#pragma unroll
    for (int it = 0; it < 8; it++) { v[it] = expf(v[it] - mm); sum += v[it]; }
#pragma unroll
    for (int o = 16; o; o >>= 1) sum += __shfl_xor_sync(0xffffffffu, sum, o);
    if ((t & 31) == 0) red[t >> 5] = sum;
    __syncthreads();
    float tot = 0.f;
#pragma unroll
    for (int w = 0; w < 8; w++) tot += red[w];
    const float inv = 1.0f / tot;

#pragma unroll
    for (int it = 0; it < 8; it++) {
        const int j = t + (it << 8);
        row[j] = v[it] * inv;   // exact 0 beyond causal bound (exp(-1e30-mm) underflows)
    }
}

// ---------------- O = attn @ V (K-loop causally truncated; longest tiles first) --------
__global__ __launch_bounds__(256) void pv_kernel(const float* attn_in)
{
    const float* attn = attn_in ? attn_in : g_attn_scratch;
    const int bcol = blockIdx.x;
    const int brow = 15 - blockIdx.y;   // LPT: longest blocks (largest kmax) dispatch first
    const int bh = blockIdx.z;
    const int b = bh >> 3, h = bh & 7;
    const float* A  = attn + (size_t)bh * Ss * Ss;
    const float* Bm = g_V + (size_t)b * Ss * HDD;
    float* C = g_O + (size_t)b * Ss * HIDD + h * HDD;
    const int kmax = brow * 128 + 128;   // rows in this tile have attn==0 beyond this
    sgemm_tile<false>(A, Ss, Bm, HDD, C, HIDD, kmax, brow, bcol, 1.f);
}

// ---------------- out = O @ wo ----------------
__global__ __launch_bounds__(256) void out_kernel(const float* __restrict__ wo, float* __restrict__ out)
{
    sgemm_tile<false>(g_O, HIDD, wo, HIDD, out, HIDD, HIDD, blockIdx.y, blockIdx.x, 1.f);
}

// ---------------- launch ----------------
extern "C" void kernel_launch(void* const* d_in, const int* in_sizes, int n_in,
                              void* d_out, int out_size)
{
    const float* x   = (const float*)d_in[0];
    // d_in[1] = attn_mask (unused: mask is exactly causal, handled analytically)
    const int*   pos = (const int*)d_in[2];
    const float* wq  = (const float*)d_in[3];
    const float* wk  = (const float*)d_in[4];
    const float* wv  = (const float*)d_in[5];
    const float* wo  = (const float*)d_in[6];
    float* out = (float*)d_out;

    const long long OUT_E  = (long long)Bb * Ss * HIDD;            //  8,388,608
    const long long ATTN_E = (long long)Bb * NHH * Ss * Ss;        // 67,108,864
    float* attn_out = ((long long)out_size >= OUT_E + ATTN_E) ? (out + OUT_E) : nullptr;

    // 1. QKV projections
    qkv_kernel<<<640, 256>>>(x, wq, wk, wv);

    // 2. RoPE
    {
        const int total = BSr * NHH * HALF + BSr * HALF;
        rope_kernel<<<(total + 255) / 256, 256>>>(pos);
    }

    // 3. scores (causal lower-triangle tiles)
    {
        dim3 g(16, 16, Bb * NHH);
        scores_kernel<<<g, 256>>>(attn_out);
    }

    // 4. softmax -> attn (second output)
    softmax_kernel<<<Bb * NHH * Ss, 256>>>(attn_out);

    // 5. O = attn @ V (longest-first dispatch)
    {
        dim3 g(2, 16, Bb * NHH);
        pv_kernel<<<g, 256>>>(attn_out);
    }

    // 6. out = O @ wo
    {
        dim3 g(16, 32);
        out_kernel<<<g, 256>>>(wo, out);
    }
}

// round 16
// speedup vs baseline: 1.0161x; 1.0161x over previous
#include <cuda_runtime.h>
#include <math.h>

#define Bb   2
#define Ss   2048
#define HIDD 2048
#define NHH  8
#define HDD  256
#define BSr  (Bb*Ss)      // 4096 rows
#define HALF (HDD/2)      // 128

// ---------------- scratch (static device memory; no allocation) ----------------
__device__ float g_Q[(size_t)BSr * HIDD];          // 32 MB  [b*S+s, h*HD+d]
__device__ float g_K[(size_t)BSr * HDD];           // 4 MB   [b*S+s, d]
__device__ float g_V[(size_t)BSr * HDD];           // 4 MB
__device__ float g_O[(size_t)BSr * HIDD];          // 32 MB  attn@V result in [b,s,h*HD+d]
__device__ float g_attn_scratch[(size_t)Bb * NHH * Ss * Ss];  // 256 MB fallback

// ---------------- f32x2 packed helpers ----------------
__device__ __forceinline__ unsigned long long pack2(float lo, float hi) {
    unsigned long long d;
    asm("mov.b64 %0, {%1, %2};" : "=l"(d) : "f"(lo), "f"(hi));
    return d;
}
__device__ __forceinline__ void unpack2(unsigned long long v, float& lo, float& hi) {
    asm("mov.b64 {%0, %1}, %2;" : "=f"(lo), "=f"(hi) : "l"(v));
}
__device__ __forceinline__ void fma2(unsigned long long& d, unsigned long long a, unsigned long long b) {
    asm("fma.rn.f32x2 %0, %1, %2, %0;" : "+l"(d) : "l"(a), "l"(b));
}

// ---------------- 128x128x8 SGEMM tile: ping-pong smem + register prefetch ----------------
// NT=false: C = A[M,K] * B[K,N]      (B row-major KxN)
// NT=true : C = A[M,K] * B[N,K]^T    (B row-major NxK)
template <bool NT>
__device__ __forceinline__ void sgemm_tile(
    const float* __restrict__ A, int lda,
    const float* __restrict__ Bm, int ldb,
    float* __restrict__ C, int ldc,
    int Kdim, int brow, int bcol, float scale)
{
    __shared__ float As[2][8][128];
    __shared__ float Bs[2][8][128];
    const int t    = threadIdx.x;
    const int tcol = t & 15;
    const int trow = t >> 4;

    unsigned long long acc[8][4];
#pragma unroll
    for (int i = 0; i < 8; i++)
#pragma unroll
        for (int j = 0; j < 4; j++) acc[i][j] = 0ull;

    const int ar = t >> 1;          // 0..127
    const int ac = (t & 1) * 4;     // 0 or 4
    const float* Abase = A + (size_t)(brow * 128 + ar) * lda + ac;
    const int br_n = t >> 5;            // NT=false: k row 0..7
    const int bc_n = (t & 31) * 4;      // NT=false: n col
    const int bn_t = t >> 1;            // NT=true : n row 0..127
    const int bk_t = (t & 1) * 4;       // NT=true : k col 0 or 4
    const float* Bbase = NT ? (Bm + (size_t)(bcol * 128 + bn_t) * ldb + bk_t)
                            : (Bm + (size_t)br_n * ldb + bcol * 128 + bc_n);

    const int nit = Kdim >> 3;

    float4 va, vb;
    va = *(const float4*)(Abase);
    vb = *(const float4*)(Bbase);
    As[0][ac + 0][ar] = va.x; As[0][ac + 1][ar] = va.y;
    As[0][ac + 2][ar] = va.z; As[0][ac + 3][ar] = va.w;
    if (!NT) {
        *(float4*)&Bs[0][br_n][bc_n] = vb;
    } else {
        Bs[0][bk_t + 0][bn_t] = vb.x; Bs[0][bk_t + 1][bn_t] = vb.y;
        Bs[0][bk_t + 2][bn_t] = vb.z; Bs[0][bk_t + 3][bn_t] = vb.w;
    }
    __syncthreads();

    for (int g = 0; g < nit; g++) {
        const int cur = g & 1;
        if (g + 1 < nit) {
            const int k = (g + 1) * 8;
            va = *(const float4*)(Abase + k);
            vb = NT ? *(const float4*)(Bbase + k)
                    : *(const float4*)(Bbase + (size_t)k * ldb);
        }

#pragma unroll
        for (int k = 0; k < 8; k++) {
            unsigned long long aa[8], bb[4];
#pragma unroll
            for (int j = 0; j < 4; j++)
                bb[j] = *(const unsigned long long*)&Bs[cur][k][2 * tcol + 32 * j];
#pragma unroll
            for (int i = 0; i < 8; i++) {
                const float a = As[cur][k][trow + 16 * i];
                aa[i] = pack2(a, a);
            }
#pragma unroll
            for (int i = 0; i < 8; i++)
#pragma unroll
                for (int j = 0; j < 4; j++)
                    fma2(acc[i][j], aa[i], bb[j]);
        }

        if (g + 1 < nit) {
            const int nxt = cur ^ 1;
            As[nxt][ac + 0][ar] = va.x; As[nxt][ac + 1][ar] = va.y;
            As[nxt][ac + 2][ar] = va.z; As[nxt][ac + 3][ar] = va.w;
            if (!NT) {
                *(float4*)&Bs[nxt][br_n][bc_n] = vb;
            } else {
                Bs[nxt][bk_t + 0][bn_t] = vb.x; Bs[nxt][bk_t + 1][bn_t] = vb.y;
                Bs[nxt][bk_t + 2][bn_t] = vb.z; Bs[nxt][bk_t + 3][bn_t] = vb.w;
            }
        }
        __syncthreads();
    }

#pragma unroll
    for (int i = 0; i < 8; i++) {
        const size_t r = (size_t)(brow * 128 + trow + 16 * i);
#pragma unroll
        for (int j = 0; j < 4; j++) {
            float lo, hi;
            unpack2(acc[i][j], lo, hi);
            const int cl = bcol * 128 + 2 * tcol + 32 * j;
            C[r * ldc + cl]     = lo * scale;
            C[r * ldc + cl + 1] = hi * scale;
        }
    }
}

// ---------------- QKV projections ----------------
__global__ __launch_bounds__(256) void qkv_kernel(
    const float* __restrict__ x,
    const float* __restrict__ wq,
    const float* __restrict__ wk,
    const float* __restrict__ wv)
{
    const int id = blockIdx.x;
    if (id < 512) {
        sgemm_tile<false>(x, HIDD, wq, HIDD, g_Q, HIDD, HIDD, id >> 4, id & 15, 1.f);
    } else if (id < 576) {
        const int m = id - 512;
        sgemm_tile<false>(x, HIDD, wk, HDD, g_K, HDD, HIDD, m >> 1, m & 1, 1.f);
    } else {
        const int m = id - 576;
        sgemm_tile<false>(x, HIDD, wv, HDD, g_V, HDD, HIDD, m >> 1, m & 1, 1.f);
    }
}

// ---------------- RoPE (fast: exact-fp64 invf via binary exponentiation, Cody-Waite
// mod-2pi reduction in fp64, fp32 sincos on the reduced argument) ----------------
__constant__ double c_BPOW[7] = {
    0.9305720409297047,    // base^1,  base = 10000^(-1/128)
    0.8659643233600654,    // base^2
    0.7498942093324559,    // base^4
    0.5623413251903491,    // base^8
    0.31622776601683794,   // base^16
    0.1,                   // base^32
    0.010000000000000002   // base^64
};
#define TWO_PI_HI 6.283185307179586
#define TWO_PI_LO 2.4492935982947064e-16
#define INV_2PI   0.15915494309189535

__device__ __forceinline__ void rope_cs(int p, int pos, float& c, float& s)
{
    double invf = 1.0;
#pragma unroll
    for (int k = 0; k < 7; k++)
        if (p & (1 << k)) invf *= c_BPOW[k];
    const double phase = (double)pos * invf;
    const double q = floor(phase * INV_2PI + 0.5);
    double r = fma(-TWO_PI_HI, q, phase);
    r = fma(-TWO_PI_LO, q, r);
    const float rf = (float)r;
    c = cosf(rf);
    s = sinf(rf);
}

__global__ void rope_kernel(const int* __restrict__ pos_ids)
{
    const int gid = blockIdx.x * blockDim.x + threadIdx.x;
    const int TQ = BSr * NHH * HALF;   // 4,194,304
    const int TK = BSr * HALF;         //   524,288
    if (gid < TQ) {
        const int p = gid & (HALF - 1);
        const int h = (gid >> 7) & (NHH - 1);
        const int r = gid >> 10;
        float c, s;
        rope_cs(p, pos_ids[r], c, s);
        float* q = g_Q + (size_t)r * HIDD + h * HDD;
        const float v1 = q[p], v2 = q[p + HALF];
        q[p]        = v1 * c - v2 * s;
        q[p + HALF] = v2 * c + v1 * s;
    } else if (gid < TQ + TK) {
        const int g2 = gid - TQ;
        const int p = g2 & (HALF - 1);
        const int r = g2 >> 7;
        float c, s;
        rope_cs(p, pos_ids[r], c, s);
        float* kk = g_K + (size_t)r * HDD;
        const float v1 = kk[p], v2 = kk[p + HALF];
        kk[p]        = v1 * c - v2 * s;
        kk[p + HALF] = v2 * c + v1 * s;
    }
}

// ---------------- scores = Q K^T / 16 (causal lower tiles) + zero-fill upper tiles -----
// Upper-triangle blocks write the exact zeros the attn output needs there; their ST
// bandwidth overlaps with neighboring blocks' FMA work (free on the fma-bound chip).
__global__ __launch_bounds__(256) void scores_kernel(float* attn_out)
{
    const int bcol = blockIdx.x, brow = blockIdx.y, bh = blockIdx.z;
    float* attn = attn_out ? attn_out : g_attn_scratch;
    float* C = attn + (size_t)bh * Ss * Ss;
    if (bcol > brow) {
        // zero-fill this 128x128 tile (rows brow*128.., cols bcol*128..)
        const int t = threadIdx.x;
        float4 z = make_float4(0.f, 0.f, 0.f, 0.f);
#pragma unroll
        for (int q = 0; q < 64; q += 8) {
            const int idx = t + (q >> 3) * 256;        // 0..2047 over 8 iterations
            const int r = idx >> 5;                    // 0..63 -> need 128 rows: 2 passes
            const int cc = (idx & 31) * 4;
            *(float4*)&C[(size_t)(brow * 128 + r) * Ss + bcol * 128 + cc] = z;
            *(float4*)&C[(size_t)(brow * 128 + 64 + r) * Ss + bcol * 128 + cc] = z;
        }
        return;
    }
    const int b = bh >> 3, h = bh & 7;
    const float* A  = g_Q + (size_t)b * Ss * HIDD + h * HDD;
    const float* Bm = g_K + (size_t)b * Ss * HDD;
    sgemm_tile<true>(A, HIDD, Bm, HDD, C, Ss, HDD, brow, bcol, 0.0625f);
}

// ---------------- causal row softmax (one pass; writes only to diagonal-tile bound) ----
__global__ __launch_bounds__(256) void softmax_kernel(float* attn_out)
{
    float* attn = attn_out ? attn_out : g_attn_scratch;
    const int R = blockIdx.x;          // (b*NH+h)*S + i
    const int i = R & (Ss - 1);
    float* row = attn + (size_t)R * Ss;
    const int n = i + 1;
    const int ru = ((i >> 7) + 1) << 7;   // cols [n, ru) must be zero (PV reads them);
                                          // cols >= ru zero-filled by scores upper tiles
    const int t = threadIdx.x;

    float v[8];
    float m = -1e30f;
#pragma unroll
    for (int it = 0; it < 8; it++) {
        const int j = t + (it << 8);
        v[it] = (j < n) ? row[j] : -1e30f;
        m = fmaxf(m, v[it]);
    }
#pragma unroll
    for (int o = 16; o; o >>= 1) m = fmaxf(m, __shfl_xor_sync(0xffffffffu, m, o));
    __shared__ float red[8];
    if ((t & 31) == 0) red[t >> 5] = m;
    __syncthreads();
    float mm = red[0];
#pragma unroll
    for (int w = 1; w < 8; w++) mm = fmaxf(mm, red[w]);
    __syncthreads();

    float sum = 0.f;
#pragma unroll
    for (int it = 0; it < 8; it++) { v[it] = expf(v[it] - mm); sum += v[it]; }
#pragma unroll
    for (int o = 16; o; o >>= 1) sum += __shfl_xor_sync(0xffffffffu, sum, o);
    if ((t & 31) == 0) red[t >> 5] = sum;
    __syncthreads();
    float tot = 0.f;
#pragma unroll
    for (int w = 0; w < 8; w++) tot += red[w];
    const float inv = 1.0f / tot;

#pragma unroll
    for (int it = 0; it < 8; it++) {
        const int j = t + (it << 8);
        if (j < ru) row[j] = v[it] * inv;   // exact 0 in [n, ru) (exp underflow)
    }
}

// ---------------- O = attn @ V (K-loop causally truncated; longest tiles first) --------
__global__ __launch_bounds__(256) void pv_kernel(const float* attn_in)
{
    const float* attn = attn_in ? attn_in : g_attn_scratch;
    const int bcol = blockIdx.x;
    const int brow = 15 - blockIdx.y;   // LPT: longest blocks (largest kmax) dispatch first
    const int bh = blockIdx.z;
    const int b = bh >> 3, h = bh & 7;
    const float* A  = attn + (size_t)bh * Ss * Ss;
    const float* Bm = g_V + (size_t)b * Ss * HDD;
    float* C = g_O + (size_t)b * Ss * HIDD + h * HDD;
    const int kmax = brow * 128 + 128;   // rows in this tile have attn==0 beyond this
    sgemm_tile<false>(A, Ss, Bm, HDD, C, HIDD, kmax, brow, bcol, 1.f);
}

// ---------------- out = O @ wo ----------------
__global__ __launch_bounds__(256) void out_kernel(const float* __restrict__ wo, float* __restrict__ out)
{
    sgemm_tile<false>(g_O, HIDD, wo, HIDD, out, HIDD, HIDD, blockIdx.y, blockIdx.x, 1.f);
}

// ---------------- launch ----------------
extern "C" void kernel_launch(void* const* d_in, const int* in_sizes, int n_in,
                              void* d_out, int out_size)
{
    const float* x   = (const float*)d_in[0];
    // d_in[1] = attn_mask (unused: mask is exactly causal, handled analytically)
    const int*   pos = (const int*)d_in[2];
    const float* wq  = (const float*)d_in[3];
    const float* wk  = (const float*)d_in[4];
    const float* wv  = (const float*)d_in[5];
    const float* wo  = (const float*)d_in[6];
    float* out = (float*)d_out;

    const long long OUT_E  = (long long)Bb * Ss * HIDD;            //  8,388,608
    const long long ATTN_E = (long long)Bb * NHH * Ss * Ss;        // 67,108,864
    float* attn_out = ((long long)out_size >= OUT_E + ATTN_E) ? (out + OUT_E) : nullptr;

    // 1. QKV projections
    qkv_kernel<<<640, 256>>>(x, wq, wk, wv);

    // 2. RoPE
    {
        const int total = BSr * NHH * HALF + BSr * HALF;
        rope_kernel<<<(total + 255) / 256, 256>>>(pos);
    }

    // 3. scores (causal lower tiles compute; upper tiles zero-fill)
    {
        dim3 g(16, 16, Bb * NHH);
        scores_kernel<<<g, 256>>>(attn_out);
    }

    // 4. softmax -> attn (second output)
    softmax_kernel<<<Bb * NHH * Ss, 256>>>(attn_out);

    // 5. O = attn @ V (longest-first dispatch)
    {
        dim3 g(2, 16, Bb * NHH);
        pv_kernel<<<g, 256>>>(attn_out);
    }

    // 6. out = O @ wo
    {
        dim3 g(16, 32);
        out_kernel<<<g, 256>>>(wo, out);
    }
}